// round 7
// baseline (speedup 1.0000x reference)
#include <cuda_runtime.h>

// ContrastiveLoss (discriminative loss), fixed shapes:
//   input_:  (4, 32, 512, 512) float32, channel-major
//   target:  (4, 1, 512, 512)  int32, labels in [0, 100)
// Output: scalar float32.

#define BB 4
#define CC 32
#define HW 262144
#define NI 100
#define HALF 50               // labels per warp half-table
#define HROWS 51              // 50 real + 1 dummy row
#define NBLK 256              // pass1 blocks per batch
#define PSZ 3300              // partial: 100*32 sums + 100 counts
#define MEANSZ 3536           // 32*104 meansT + 104 msq + 104 invc
#define MP 104                // transposed means pitch
#define STREAM 128            // k_var streaming blocks per batch
#define DVAR 0.75f
#define REP 4.0f              // 2 * DELTA_DIST

__device__ float g_part[BB * NBLK * PSZ];   // 13.5 MB raw per-block tables
__device__ float g_mean[BB * MEANSZ];       // meansT + ||m||^2 + 1/cnt

// ---------------------------------------------------------------------------
// Pass 1: label-split accumulation. Block = 64 thr (2 warps) sharing one
// staged 64-px tile; warp w owns labels [50w, 50w+50). Every pixel updates
// branchlessly: out-of-range labels are redirected to a dummy row, so the
// smem RMW stream has no divergence and ~2x the chain-slots/SM of R6.
// Counts via __match_any_sync leader adds (no per-pixel count chain).
__global__ void __launch_bounds__(64) k_pass1(const float* __restrict__ in,
                                              const int* __restrict__ tgt) {
    __shared__ float T2[2][HROWS * 32];           // 13.1 KB
    __shared__ float Cn[2][HALF];                 // 400 B
    __shared__ float TL[64 * 33];                 // 8.45 KB, [px][c]
    __shared__ __align__(16) int L[64];

    const int b    = blockIdx.y;
    const int tid  = threadIdx.x;
    const int warp = tid >> 5;
    const int lane = tid & 31;
    float* T  = T2[warp];
    float* Cw = Cn[warp];

    for (int i = tid; i < 2 * HROWS * 32; i += 64) (&T2[0][0])[i] = 0.0f;
    for (int i = tid; i < 2 * HALF; i += 64)       (&Cn[0][0])[i] = 0.0f;
    __syncthreads();

    const int*   tb  = tgt + (size_t)b * HW;
    const float* inb = in  + (size_t)b * CC * HW;
    const int base = blockIdx.x * 1024;
    const int lo   = warp * HALF;

    for (int ch = 0; ch < 16; ++ch) {
        const int p0 = base + ch * 64;
        if (tid < 16) ((int4*)L)[tid] = ((const int4*)(tb + p0))[tid];
        // stage 64 px x 32 ch, coalesced LDG, transposed STS (pitch 33)
        const float* src = inb + p0 + tid;
#pragma unroll
        for (int c = 0; c < CC; ++c)
            TL[tid * 33 + c] = src[(size_t)c * HW];
        __syncthreads();

        // counts: one leader add per distinct label per 32-label round
#pragma unroll
        for (int h = 0; h < 2; ++h) {
            const int l = L[h * 32 + lane];
            const unsigned grp = __match_any_sync(0xffffffffu, l);
            if ((unsigned)(l - lo) < (unsigned)HALF &&
                lane == __ffs(grp) - 1)
                Cw[l - lo] += (float)__popc(grp);
        }

        // sums: branchless, dummy row 50 absorbs the other warp's labels
#pragma unroll
        for (int j = 0; j < 64; ++j) {
            const int d = L[j] - lo;
            const int r = ((unsigned)d < (unsigned)HALF) ? d : HALF;
            T[r * 32 + lane] += TL[j * 33 + lane];
        }
        __syncthreads();
    }

    // flush partials (rows 0..99 from the two half-tables, then counts)
    float* dst = g_part + (size_t)(b * NBLK + blockIdx.x) * PSZ;
    for (int i = tid; i < NI * 32; i += 64) {
        const int l = i >> 5, c = i & 31;
        dst[i] = (l < HALF) ? T2[0][l * 32 + c]
                            : T2[1][(l - HALF) * 32 + c];
    }
    for (int i = tid; i < NI; i += 64)
        dst[NI * 32 + i] = (&Cn[0][0])[i];
}

// ---------------------------------------------------------------------------
// Reduce 256 partials/batch -> transposed means + ||m||^2 + 1/cnt.
// Grid (100, 4) [block = one label], 160 threads: groups 0-3 sum channel
// partials over k-quarters, group 4 sums counts. Also zeroes out[0].
__global__ void __launch_bounds__(160) k_reduce(float* __restrict__ out) {
    __shared__ float ssum[4][32];
    __shared__ float scnt;

    const int b = blockIdx.y, l = blockIdx.x;
    const int t = threadIdx.x, g = t >> 5, lane = t & 31;
    const float* base = g_part + (size_t)b * NBLK * PSZ;

    if (g < 4) {
        float s = 0.0f;
        const float* p = base + l * 32 + lane;
#pragma unroll 8
        for (int k = g * 64; k < g * 64 + 64; ++k) s += p[(size_t)k * PSZ];
        ssum[g][lane] = s;
    } else {
        float s = 0.0f;
        const float* p = base + NI * 32 + l;
#pragma unroll
        for (int i = 0; i < 8; ++i) s += p[(size_t)(lane * 8 + i) * PSZ];
#pragma unroll
        for (int o = 16; o > 0; o >>= 1) s += __shfl_down_sync(0xffffffffu, s, o);
        if (lane == 0) scnt = s;
    }
    __syncthreads();

    if (t < 32) {
        const float cntv = scnt;
        const float m = (ssum[0][t] + ssum[1][t] + ssum[2][t] + ssum[3][t]) / cntv;
        g_mean[b * MEANSZ + t * MP + l] = m;           // transposed: [c][l]
        float q = m * m;
#pragma unroll
        for (int o = 16; o > 0; o >>= 1) q += __shfl_down_sync(0xffffffffu, q, o);
        if (t == 0) {
            g_mean[b * MEANSZ + 32 * MP + l]       = q;           // ||m||^2
            g_mean[b * MEANSZ + 32 * MP + 104 + l] = 1.0f / cntv; // 1/cnt
        }
    }
    if (b == 0 && l == 0 && t == 33) out[0] = 0.0f;
}

// ---------------------------------------------------------------------------
// Pass 2: variance via ||f-m||^2 = ||f||^2 - 2 f.m + ||m||^2.
// Means table replicated 2x in smem (lane parity picks the copy, 16-bank
// offset) -> gather conflicts ~2-way, under the HBM pace.
// Blocks 0..127/batch stream 2048 px each; block 128 does pairs + reg term.
__global__ void __launch_bounds__(512) k_var(const float* __restrict__ in,
                                             const int* __restrict__ tgt,
                                             float* __restrict__ out) {
    __shared__ float sm[2 * MEANSZ];   // 28.3 KB
    __shared__ float red[16];

    const int b = blockIdx.y;
    for (int i = threadIdx.x; i < MEANSZ; i += 512) {
        const float v = g_mean[b * MEANSZ + i];
        sm[i] = v;
        sm[MEANSZ + i] = v;
    }
    __syncthreads();

    float acc = 0.0f;
    if (blockIdx.x < STREAM) {
        const float* S = sm + (threadIdx.x & 1) * MEANSZ;
        const float* s_msq  = S + 32 * MP;
        const float* s_invc = S + 32 * MP + 104;
        const float* inb = in  + (size_t)b * CC * HW;
        const int*   tb  = tgt + (size_t)b * HW;
        const int p0 = blockIdx.x * 2048 + threadIdx.x;
#pragma unroll
        for (int k = 0; k < 4; ++k) {
            const int p = p0 + k * 512;
            const int l = tb[p];
            const float* fp = inb + p;
            float f2 = 0.0f, fd = 0.0f;
#pragma unroll
            for (int c = 0; c < CC; ++c) {
                const float f = fp[(size_t)c * HW];
                const float m = S[c * MP + l];
                f2 = fmaf(f, f, f2);
                fd = fmaf(f, m, fd);
            }
            const float d2 = fmaxf(f2 - 2.0f * fd + s_msq[l], 0.0f);
            const float r  = sqrtf(d2);
            const float h  = fmaxf(r - DVAR, 0.0f);
            acc = fmaf(h * h, s_invc[l], acc);
        }
        acc *= (1.0f / (NI * BB));                         // ALPHA = 1
    } else {
        // distance term (9900 ordered pairs) + regularizer
        float accd = 0.0f, accr = 0.0f;
        for (int idx = threadIdx.x; idx < NI * NI; idx += 512) {
            const int i = idx / NI, j = idx - i * NI;
            if (i == j) continue;
            float d2 = 0.0f;
#pragma unroll
            for (int c = 0; c < CC; ++c) {
                const float v = sm[c * MP + i] - sm[c * MP + j];
                d2 = fmaf(v, v, d2);
            }
            const float d = (d2 > 0.0f) ? sqrtf(d2) : 1.0f;
            const float h = fmaxf(REP - d, 0.0f);
            accd = fmaf(h, h, accd);
        }
        if (threadIdx.x < NI) accr = sqrtf(sm[32 * MP + threadIdx.x]);
        acc = accd * (1.0f / (NI * (NI - 1) * BB))          // BETA = 1
            + accr * (0.001f / (NI * BB));                  // GAMMA = 0.001
    }

#pragma unroll
    for (int o = 16; o > 0; o >>= 1) acc += __shfl_down_sync(0xffffffffu, acc, o);
    if ((threadIdx.x & 31) == 0) red[threadIdx.x >> 5] = acc;
    __syncthreads();
    if (threadIdx.x < 32) {
        float v = (threadIdx.x < 16) ? red[threadIdx.x] : 0.0f;
#pragma unroll
        for (int o = 8; o > 0; o >>= 1) v += __shfl_down_sync(0xffffffffu, v, o);
        if (threadIdx.x == 0) atomicAdd(out, v);
    }
}

// ---------------------------------------------------------------------------
extern "C" void kernel_launch(void* const* d_in, const int* in_sizes, int n_in,
                              void* d_out, int out_size) {
    const float* in  = (const float*)d_in[0];
    const int*   tgt = (const int*)d_in[1];
    float* out = (float*)d_out;

    dim3 g1(NBLK, BB);
    k_pass1<<<g1, 64>>>(in, tgt);
    dim3 gr(NI, BB);
    k_reduce<<<gr, 160>>>(out);
    dim3 g2(STREAM + 1, BB);
    k_var<<<g2, 512>>>(in, tgt, out);
}

// round 8
// speedup vs baseline: 1.4200x; 1.4200x over previous
#include <cuda_runtime.h>

// ContrastiveLoss (discriminative loss), fixed shapes:
//   input_:  (4, 32, 512, 512) float32, channel-major
//   target:  (4, 1, 512, 512)  int32, labels in [0, 100)
// Output: scalar float32.

#define BB 4
#define CC 32
#define HW 262144
#define NI 100
#define ROWS 101              // 100 real + 1 dummy row (duplicate redirect)
#define NBLK 256              // pass1 blocks per batch
#define PSZ 3300              // partial: 100*32 sums + 100 counts
#define MEANSZ 3536           // 32*104 meansT + 104 msq + 104 invc
#define MP 104                // transposed means pitch
#define DVAR 0.75f
#define REP 4.0f              // 2 * DELTA_DIST

__device__ float g_part[BB * NBLK * PSZ];   // 13.5 MB raw per-block tables
__device__ float g_mean[BB * MEANSZ];       // meansT + ||m||^2 + 1/cnt

// ---------------------------------------------------------------------------
// 4-pixel batched RMW with duplicate-merge. After dedup the 4 row indices are
// distinct (dupes redirected to dummy row 100, where lost updates are fine),
// so the 4 LDS are independent -> 4-wide MLP instead of a serial 29-cyc chain.
__device__ __forceinline__ void rmw4(float* __restrict__ T, int lane,
                                     int l0, int l1, int l2, int l3,
                                     float v0, float v1, float v2, float v3) {
    if (l1 == l0)      { v0 += v1; v1 = 0.0f; l1 = NI; }
    if (l2 == l0)      { v0 += v2; v2 = 0.0f; l2 = NI; }
    else if (l2 == l1) { v1 += v2; v2 = 0.0f; l2 = NI; }
    if (l3 == l0)      { v0 += v3; v3 = 0.0f; l3 = NI; }
    else if (l3 == l1) { v1 += v3; v3 = 0.0f; l3 = NI; }
    else if (l3 == l2) { v2 += v3; v3 = 0.0f; l3 = NI; }

    const int a0 = l0 * 32 + lane, a1 = l1 * 32 + lane;
    const int a2 = l2 * 32 + lane, a3 = l3 * 32 + lane;
    const float t0 = T[a0], t1 = T[a1], t2 = T[a2], t3 = T[a3];
    T[a0] = t0 + v0;  T[a1] = t1 + v1;  T[a2] = t2 + v2;  T[a3] = t3 + v3;
}

// ---------------------------------------------------------------------------
// Pass 1: per-label channel sums + counts, warp-private tables (R6 layout:
// lane = channel, pitch 32 -> always conflict-free) with 4-wide dedup
// batching. Counts via __match_any leader adds. Grid (256, 4), block 64
// (2 warps), 512 px/warp in 16 chunks of 32.
__global__ void __launch_bounds__(64) k_pass1(const float* __restrict__ in,
                                              const int* __restrict__ tgt) {
    __shared__ float tab[2][ROWS * 32];            // 25.9 KB
    __shared__ float cnt[2][104];                  // 0.8 KB
    __shared__ float tile[2][32 * 33];             // 8.45 KB, [px][c]
    __shared__ __align__(16) int lab[2][32];

    const int b    = blockIdx.y;
    const int warp = threadIdx.x >> 5;
    const int lane = threadIdx.x & 31;
    float* T  = tab[warp];
    float* Cw = cnt[warp];
    float* TL = tile[warp];
    int*   L  = lab[warp];

    for (int i = threadIdx.x; i < 2 * ROWS * 32; i += 64) (&tab[0][0])[i] = 0.0f;
    for (int i = threadIdx.x; i < 2 * 104; i += 64)       (&cnt[0][0])[i] = 0.0f;
    __syncthreads();

    const int*   tb  = tgt + (size_t)b * HW;
    const float* inb = in  + (size_t)b * CC * HW;
    const int base = (blockIdx.x * 2 + warp) * 512;

    for (int ch = 0; ch < 16; ++ch) {
        const int p0 = base + ch * 32;
        if (lane < 8) ((int4*)L)[lane] = ((const int4*)(tb + p0))[lane];
        // stage: coalesced LDG (lane = pixel), transposed STS, pitch 33
        const float* src = inb + p0 + lane;
#pragma unroll
        for (int c = 0; c < CC; ++c)
            TL[lane * 33 + c] = src[(size_t)c * HW];
        __syncwarp();

        // counts: one leader add per distinct label in this 32-px chunk
        {
            const int l = L[lane];
            const unsigned grp = __match_any_sync(0xffffffffu, l);
            if (lane == __ffs(grp) - 1) Cw[l] += (float)__popc(grp);
        }

        // sums: 8 batches of 4 pixels, dedup -> independent smem chains
#pragma unroll
        for (int g = 0; g < 8; ++g) {
            const int4 Lg = *(const int4*)(L + g * 4);   // broadcast LDS.128
            const float v0 = TL[(4 * g + 0) * 33 + lane];
            const float v1 = TL[(4 * g + 1) * 33 + lane];
            const float v2 = TL[(4 * g + 2) * 33 + lane];
            const float v3 = TL[(4 * g + 3) * 33 + lane];
            rmw4(T, lane, Lg.x, Lg.y, Lg.z, Lg.w, v0, v1, v2, v3);
        }
        __syncwarp();
    }
    __syncthreads();

    // flush raw partials (plain coalesced stores, no atomics)
    float* dst = g_part + (size_t)(b * NBLK + blockIdx.x) * PSZ;
    for (int i = threadIdx.x; i < NI * 32; i += 64)
        dst[i] = tab[0][i] + tab[1][i];
    for (int i = threadIdx.x; i < NI; i += 64)
        dst[NI * 32 + i] = cnt[0][i] + cnt[1][i];
}

// ---------------------------------------------------------------------------
// Reduce 256 partials/batch -> transposed means + ||m||^2 + 1/cnt.
// Grid (100, 4) [block = one label], 160 threads. Also zeroes out[0].
__global__ void __launch_bounds__(160) k_reduce(float* __restrict__ out) {
    __shared__ float ssum[4][32];
    __shared__ float scnt;

    const int b = blockIdx.y, l = blockIdx.x;
    const int t = threadIdx.x, g = t >> 5, lane = t & 31;
    const float* base = g_part + (size_t)b * NBLK * PSZ;

    if (g < 4) {
        float s = 0.0f;
        const float* p = base + l * 32 + lane;
#pragma unroll 8
        for (int k = g * 64; k < g * 64 + 64; ++k) s += p[(size_t)k * PSZ];
        ssum[g][lane] = s;
    } else {
        float s = 0.0f;
        const float* p = base + NI * 32 + l;
#pragma unroll
        for (int i = 0; i < 8; ++i) s += p[(size_t)(lane * 8 + i) * PSZ];
#pragma unroll
        for (int o = 16; o > 0; o >>= 1) s += __shfl_down_sync(0xffffffffu, s, o);
        if (lane == 0) scnt = s;
    }
    __syncthreads();

    if (t < 32) {
        const float cntv = scnt;
        const float m = (ssum[0][t] + ssum[1][t] + ssum[2][t] + ssum[3][t]) / cntv;
        g_mean[b * MEANSZ + t * MP + l] = m;           // transposed: [c][l]
        float q = m * m;
#pragma unroll
        for (int o = 16; o > 0; o >>= 1) q += __shfl_down_sync(0xffffffffu, q, o);
        if (t == 0) {
            g_mean[b * MEANSZ + 32 * MP + l]       = q;           // ||m||^2
            g_mean[b * MEANSZ + 32 * MP + 104 + l] = 1.0f / cntv; // 1/cnt
        }
    }
    if (b == 0 && l == 0 && t == 33) out[0] = 0.0f;
}

// ---------------------------------------------------------------------------
// Pass 2: variance via ||f-m||^2 = ||f||^2 - 2 f.m + ||m||^2 (scalar LDS
// gathers from transposed means). Blocks 0..63/batch stream 4096 px each;
// block 64 does the pairwise-distance + regularizer terms.
__global__ void __launch_bounds__(512) k_var(const float* __restrict__ in,
                                             const int* __restrict__ tgt,
                                             float* __restrict__ out) {
    __shared__ float sm[MEANSZ];     // 14.1 KB: meansT | msq | invc
    __shared__ float red[16];

    const int b = blockIdx.y;
    for (int i = threadIdx.x; i < MEANSZ; i += 512)
        sm[i] = g_mean[b * MEANSZ + i];
    __syncthreads();
    const float* s_msq  = sm + 32 * MP;
    const float* s_invc = sm + 32 * MP + 104;

    float acc = 0.0f;
    if (blockIdx.x < 64) {
        const float* inb = in  + (size_t)b * CC * HW;
        const int*   tb  = tgt + (size_t)b * HW;
        const int p0 = blockIdx.x * 4096 + threadIdx.x;
#pragma unroll
        for (int k = 0; k < 8; ++k) {
            const int p = p0 + k * 512;
            const int l = tb[p];
            const float* fp = inb + p;
            float f2 = 0.0f, fd = 0.0f;
#pragma unroll
            for (int c = 0; c < CC; ++c) {
                const float f = fp[(size_t)c * HW];
                const float m = sm[c * MP + l];
                f2 = fmaf(f, f, f2);
                fd = fmaf(f, m, fd);
            }
            const float d2 = fmaxf(f2 - 2.0f * fd + s_msq[l], 0.0f);
            const float r  = sqrtf(d2);
            const float h  = fmaxf(r - DVAR, 0.0f);
            acc = fmaf(h * h, s_invc[l], acc);
        }
        acc *= (1.0f / (NI * BB));                         // ALPHA = 1
    } else {
        // distance term (9900 ordered pairs) + regularizer
        float accd = 0.0f, accr = 0.0f;
        for (int idx = threadIdx.x; idx < NI * NI; idx += 512) {
            const int i = idx / NI, j = idx - i * NI;
            if (i == j) continue;
            float d2 = 0.0f;
#pragma unroll
            for (int c = 0; c < CC; ++c) {
                const float v = sm[c * MP + i] - sm[c * MP + j];
                d2 = fmaf(v, v, d2);
            }
            const float d = (d2 > 0.0f) ? sqrtf(d2) : 1.0f;
            const float h = fmaxf(REP - d, 0.0f);
            accd = fmaf(h, h, accd);
        }
        if (threadIdx.x < NI) accr = sqrtf(s_msq[threadIdx.x]);
        acc = accd * (1.0f / (NI * (NI - 1) * BB))          // BETA = 1
            + accr * (0.001f / (NI * BB));                  // GAMMA = 0.001
    }

#pragma unroll
    for (int o = 16; o > 0; o >>= 1) acc += __shfl_down_sync(0xffffffffu, acc, o);
    if ((threadIdx.x & 31) == 0) red[threadIdx.x >> 5] = acc;
    __syncthreads();
    if (threadIdx.x < 32) {
        float v = (threadIdx.x < 16) ? red[threadIdx.x] : 0.0f;
#pragma unroll
        for (int o = 8; o > 0; o >>= 1) v += __shfl_down_sync(0xffffffffu, v, o);
        if (threadIdx.x == 0) atomicAdd(out, v);
    }
}

// ---------------------------------------------------------------------------
extern "C" void kernel_launch(void* const* d_in, const int* in_sizes, int n_in,
                              void* d_out, int out_size) {
    const float* in  = (const float*)d_in[0];
    const int*   tgt = (const int*)d_in[1];
    float* out = (float*)d_out;

    dim3 g1(NBLK, BB);
    k_pass1<<<g1, 64>>>(in, tgt);
    dim3 gr(NI, BB);
    k_reduce<<<gr, 160>>>(out);
    dim3 g2(65, BB);
    k_var<<<g2, 512>>>(in, tgt, out);
}

// round 9
// speedup vs baseline: 1.7873x; 1.2586x over previous
#include <cuda_runtime.h>

// ContrastiveLoss (discriminative loss), fixed shapes:
//   input_:  (4, 32, 512, 512) float32, channel-major
//   target:  (4, 1, 512, 512)  int32, labels in [0, 100)
// Output: scalar float32.

#define BB 4
#define CC 32
#define HW 262144
#define NI 100
#define NBLK 256              // pass1 blocks per batch
#define PSZ 3300              // partial: 100*32 sums + 100 counts
#define MEANSZ 3536           // 32*104 meansT + 104 msq + 104 invc
#define MP 104                // transposed means pitch
#define STREAM 128            // k_var streaming blocks per batch
#define DVAR 0.75f
#define REP 4.0f              // 2 * DELTA_DIST

__device__ float g_part[BB * NBLK * PSZ];   // 13.5 MB raw per-block tables
__device__ float g_mean[BB * MEANSZ];       // meansT + ||m||^2 + 1/cnt

// ---------------------------------------------------------------------------
// Pass 1: per-label channel sums + counts via fire-and-forget shared-memory
// atomics (no LDS->FADD->STS dependency chain, no dedup ALU). One table per
// block (atomics make cross-warp sharing safe) -> 31 KB/block, 128 threads,
// 7 blocks/SM = 28 warps. Addresses T[l*32+lane] are bank-spread (bank=lane).
// Grid (256, 4); warp owns 256 px in 8 staged chunks of 32.
__global__ void __launch_bounds__(128) k_pass1(const float* __restrict__ in,
                                               const int* __restrict__ tgt) {
    __shared__ float T[NI * 32];                   // 12.8 KB, block-shared
    __shared__ float Cn[NI];                       // 400 B
    __shared__ float tile[4][32 * 33];             // 16.9 KB, [warp][px][c]
    __shared__ __align__(16) int lab[4][32];

    const int b    = blockIdx.y;
    const int tid  = threadIdx.x;
    const int warp = tid >> 5;
    const int lane = tid & 31;
    float* TL = tile[warp];
    int*   L  = lab[warp];

    for (int i = tid; i < NI * 32; i += 128) T[i] = 0.0f;
    if (tid < NI) Cn[tid] = 0.0f;
    __syncthreads();

    const int*   tb  = tgt + (size_t)b * HW;
    const float* inb = in  + (size_t)b * CC * HW;
    const int base = blockIdx.x * 1024 + warp * 256;

    for (int ch = 0; ch < 8; ++ch) {
        const int p0 = base + ch * 32;
        if (lane < 8) ((int4*)L)[lane] = ((const int4*)(tb + p0))[lane];
        // stage: coalesced LDG (lane = pixel), transposed STS, pitch 33
        const float* src = inb + p0 + lane;
#pragma unroll
        for (int c = 0; c < CC; ++c)
            TL[lane * 33 + c] = src[(size_t)c * HW];
        __syncwarp();

        // counts: one leader atomic per distinct label in this chunk
        {
            const int l = L[lane];
            const unsigned grp = __match_any_sync(0xffffffffu, l);
            if (lane == __ffs(grp) - 1)
                atomicAdd(&Cn[l], (float)__popc(grp));
        }

        // sums: 1 ATOMS per pixel, fully pipelined (no RMW chain)
#pragma unroll
        for (int g = 0; g < 8; ++g) {
            const int4 Lg = *(const int4*)(L + g * 4);   // broadcast LDS.128
            atomicAdd(&T[Lg.x * 32 + lane], TL[(4 * g + 0) * 33 + lane]);
            atomicAdd(&T[Lg.y * 32 + lane], TL[(4 * g + 1) * 33 + lane]);
            atomicAdd(&T[Lg.z * 32 + lane], TL[(4 * g + 2) * 33 + lane]);
            atomicAdd(&T[Lg.w * 32 + lane], TL[(4 * g + 3) * 33 + lane]);
        }
        __syncwarp();
    }
    __syncthreads();

    // flush raw partials (plain coalesced stores, no global atomics)
    float* dst = g_part + (size_t)(b * NBLK + blockIdx.x) * PSZ;
    for (int i = tid; i < NI * 32; i += 128) dst[i] = T[i];
    if (tid < NI) dst[NI * 32 + tid] = Cn[tid];
}

// ---------------------------------------------------------------------------
// Reduce 256 partials/batch -> transposed means + ||m||^2 + 1/cnt.
// Grid (100, 4) [block = one label], 160 threads. Also zeroes out[0].
__global__ void __launch_bounds__(160) k_reduce(float* __restrict__ out) {
    __shared__ float ssum[4][32];
    __shared__ float scnt;

    const int b = blockIdx.y, l = blockIdx.x;
    const int t = threadIdx.x, g = t >> 5, lane = t & 31;
    const float* base = g_part + (size_t)b * NBLK * PSZ;

    if (g < 4) {
        float s = 0.0f;
        const float* p = base + l * 32 + lane;
#pragma unroll 8
        for (int k = g * 64; k < g * 64 + 64; ++k) s += p[(size_t)k * PSZ];
        ssum[g][lane] = s;
    } else {
        float s = 0.0f;
        const float* p = base + NI * 32 + l;
#pragma unroll
        for (int i = 0; i < 8; ++i) s += p[(size_t)(lane * 8 + i) * PSZ];
#pragma unroll
        for (int o = 16; o > 0; o >>= 1) s += __shfl_down_sync(0xffffffffu, s, o);
        if (lane == 0) scnt = s;
    }
    __syncthreads();

    if (t < 32) {
        const float cntv = scnt;
        const float m = (ssum[0][t] + ssum[1][t] + ssum[2][t] + ssum[3][t]) / cntv;
        g_mean[b * MEANSZ + t * MP + l] = m;           // transposed: [c][l]
        float q = m * m;
#pragma unroll
        for (int o = 16; o > 0; o >>= 1) q += __shfl_down_sync(0xffffffffu, q, o);
        if (t == 0) {
            g_mean[b * MEANSZ + 32 * MP + l]       = q;           // ||m||^2
            g_mean[b * MEANSZ + 32 * MP + 104 + l] = 1.0f / cntv; // 1/cnt
        }
    }
    if (b == 0 && l == 0 && t == 33) out[0] = 0.0f;
}

// ---------------------------------------------------------------------------
// Pass 2: variance via ||f-m||^2 = ||f||^2 - 2 f.m + ||m||^2 (scalar LDS
// gathers from transposed means). Blocks 0..127/batch stream 2048 px each;
// block 128 does the pairwise-distance + regularizer terms.
__global__ void __launch_bounds__(512) k_var(const float* __restrict__ in,
                                             const int* __restrict__ tgt,
                                             float* __restrict__ out) {
    __shared__ float sm[MEANSZ];     // 14.1 KB: meansT | msq | invc
    __shared__ float red[16];

    const int b = blockIdx.y;
    for (int i = threadIdx.x; i < MEANSZ; i += 512)
        sm[i] = g_mean[b * MEANSZ + i];
    __syncthreads();
    const float* s_msq  = sm + 32 * MP;
    const float* s_invc = sm + 32 * MP + 104;

    float acc = 0.0f;
    if (blockIdx.x < STREAM) {
        const float* inb = in  + (size_t)b * CC * HW;
        const int*   tb  = tgt + (size_t)b * HW;
        const int p0 = blockIdx.x * 2048 + threadIdx.x;
#pragma unroll
        for (int k = 0; k < 4; ++k) {
            const int p = p0 + k * 512;
            const int l = tb[p];
            const float* fp = inb + p;
            float f2 = 0.0f, fd = 0.0f;
#pragma unroll
            for (int c = 0; c < CC; ++c) {
                const float f = fp[(size_t)c * HW];
                const float m = sm[c * MP + l];
                f2 = fmaf(f, f, f2);
                fd = fmaf(f, m, fd);
            }
            const float d2 = fmaxf(f2 - 2.0f * fd + s_msq[l], 0.0f);
            const float r  = sqrtf(d2);
            const float h  = fmaxf(r - DVAR, 0.0f);
            acc = fmaf(h * h, s_invc[l], acc);
        }
        acc *= (1.0f / (NI * BB));                         // ALPHA = 1
    } else {
        // distance term (9900 ordered pairs) + regularizer
        float accd = 0.0f, accr = 0.0f;
        for (int idx = threadIdx.x; idx < NI * NI; idx += 512) {
            const int i = idx / NI, j = idx - i * NI;
            if (i == j) continue;
            float d2 = 0.0f;
#pragma unroll
            for (int c = 0; c < CC; ++c) {
                const float v = sm[c * MP + i] - sm[c * MP + j];
                d2 = fmaf(v, v, d2);
            }
            const float d = (d2 > 0.0f) ? sqrtf(d2) : 1.0f;
            const float h = fmaxf(REP - d, 0.0f);
            accd = fmaf(h, h, accd);
        }
        if (threadIdx.x < NI) accr = sqrtf(s_msq[threadIdx.x]);
        acc = accd * (1.0f / (NI * (NI - 1) * BB))          // BETA = 1
            + accr * (0.001f / (NI * BB));                  // GAMMA = 0.001
    }

#pragma unroll
    for (int o = 16; o > 0; o >>= 1) acc += __shfl_down_sync(0xffffffffu, acc, o);
    if ((threadIdx.x & 31) == 0) red[threadIdx.x >> 5] = acc;
    __syncthreads();
    if (threadIdx.x < 32) {
        float v = (threadIdx.x < 16) ? red[threadIdx.x] : 0.0f;
#pragma unroll
        for (int o = 8; o > 0; o >>= 1) v += __shfl_down_sync(0xffffffffu, v, o);
        if (threadIdx.x == 0) atomicAdd(out, v);
    }
}

// ---------------------------------------------------------------------------
extern "C" void kernel_launch(void* const* d_in, const int* in_sizes, int n_in,
                              void* d_out, int out_size) {
    const float* in  = (const float*)d_in[0];
    const int*   tgt = (const int*)d_in[1];
    float* out = (float*)d_out;

    dim3 g1(NBLK, BB);
    k_pass1<<<g1, 128>>>(in, tgt);
    dim3 gr(NI, BB);
    k_reduce<<<gr, 160>>>(out);
    dim3 g2(STREAM + 1, BB);
    k_var<<<g2, 512>>>(in, tgt, out);
}